// round 14
// baseline (speedup 1.0000x reference)
#include <cuda_runtime.h>
#include <math.h>

#define S_TOT   2048
#define N_TOT   32768
#define NPAIRS  (N_TOT / 2)   // 16384 float4 columns
#define NPB     256           // n-pairs per block (512 n)
#define NFLOWS  30
#define SCHUNK  128           // s-samples handled per block
#define TPB     256

__device__ __forceinline__ float softplus_f(float x) {
    return (x > 0.0f) ? (x + log1pf(expf(-x))) : log1pf(expf(x));
}

// tiny 10->10->10->2 MLP with relu/relu/tanh, weights in smem
__device__ __forceinline__ void mlp2(const float* __restrict__ Y, int n,
                                     const float* sW1, const float* sB1,
                                     const float* sW2, const float* sB2,
                                     const float* sW3, const float* sB3,
                                     float& f0, float& f1) {
    float y[10];
    #pragma unroll
    for (int i = 0; i < 10; i++) y[i] = Y[n * 10 + i];
    float h1[10];
    #pragma unroll
    for (int j = 0; j < 10; j++) {
        float acc = sB1[j];
        #pragma unroll
        for (int i = 0; i < 10; i++) acc = fmaf(y[i], sW1[i * 10 + j], acc);
        h1[j] = fmaxf(acc, 0.0f);
    }
    float h2[10];
    #pragma unroll
    for (int j = 0; j < 10; j++) {
        float acc = sB2[j];
        #pragma unroll
        for (int i = 0; i < 10; i++) acc = fmaf(h1[i], sW2[i * 10 + j], acc);
        h2[j] = fmaxf(acc, 0.0f);
    }
    float a0 = sB3[0], a1 = sB3[1];
    #pragma unroll
    for (int j = 0; j < 10; j++) {
        a0 = fmaf(h2[j], sW3[j * 2 + 0], a0);
        a1 = fmaf(h2[j], sW3[j * 2 + 1], a1);
    }
    f0 = tanhf(a0);
    f1 = tanhf(a1);
}

__global__ __launch_bounds__(TPB)       // NO min-blocks cap (R6 lesson)
void encoder_fused_kernel(
    const float* __restrict__ eps,      // [S,4]
    const float* __restrict__ mu,       // [4]
    const float* __restrict__ sigma,    // [4]
    const float* __restrict__ x0,       // [30,4]
    const float* __restrict__ ap,       // [30]
    const float* __restrict__ bp,       // [30]
    const float* __restrict__ Y,        // [N,10]
    const float* __restrict__ W1, const float* __restrict__ b1,
    const float* __restrict__ W2, const float* __restrict__ b2,
    const float* __restrict__ W3, const float* __restrict__ b3,
    float* __restrict__ out)            // [S,N,2]
{
    __shared__ float sW1[100], sW2[100], sW3[20];
    __shared__ float sB1[10], sB2[10], sB3[2];
    __shared__ float sx0[NFLOWS * 4];
    __shared__ float sAl[NFLOWS], sBe[NFLOWS];
    __shared__ float4 sZ[SCHUNK];
    __shared__ float4 sF[NPB];           // f for 256 n-pairs, 4 KB

    const int tid = threadIdx.x;

    // ---- cooperative parameter staging ----
    if (tid < 100) { sW1[tid] = W1[tid]; sW2[tid] = W2[tid]; }
    if (tid < 20)  { sW3[tid] = W3[tid]; }
    if (tid < 10)  { sB1[tid] = b1[tid]; sB2[tid] = b2[tid]; }
    if (tid < 2)   { sB3[tid] = b3[tid]; }
    if (tid < NFLOWS * 4) { sx0[tid] = x0[tid]; }
    if (tid < NFLOWS) {
        float a = softplus_f(ap[tid]);
        sAl[tid] = a;
        sBe[tid] = -a + softplus_f(bp[tid]);
    }
    __syncthreads();

    // ---- radial flow for this block's s-chunk (threads 0..127) ----
    const int s_base = blockIdx.y * SCHUNK;
    if (tid < SCHUNK) {
        const int s = s_base + tid;
        const float4 e = reinterpret_cast<const float4*>(eps)[s];  // LDG.128
        float z0 = fmaf(tanhf(sigma[0]) + 1.0f, e.x, 3.0f * tanhf(mu[0]));
        float z1 = fmaf(tanhf(sigma[1]) + 1.0f, e.y, 3.0f * tanhf(mu[1]));
        float z2 = fmaf(tanhf(sigma[2]) + 1.0f, e.z, 3.0f * tanhf(mu[2]));
        float z3 = fmaf(tanhf(sigma[3]) + 1.0f, e.w, 3.0f * tanhf(mu[3]));
        #pragma unroll 1
        for (int k = 0; k < NFLOWS; k++) {
            const float a  = sAl[k];
            const float be = sBe[k];
            const float d0 = z0 - sx0[k * 4 + 0];
            const float d1 = z1 - sx0[k * 4 + 1];
            const float d2 = z2 - sx0[k * 4 + 2];
            const float d3 = z3 - sx0[k * 4 + 3];
            const float r  = sqrtf(fmaf(d0, d0, fmaf(d1, d1, fmaf(d2, d2, d3 * d3))));
            const float bh = __fdividef(be, a + r);   // fast rcp path
            z0 = fmaf(bh, d0, z0);
            z1 = fmaf(bh, d1, z1);
            z2 = fmaf(bh, d2, z2);
            z3 = fmaf(bh, d3, z3);
        }
        sZ[tid] = make_float4(z0, z1, z2, z3);
    }

    // ---- per-thread MLP for two adjacent n -> sF (R9's proven prologue) ----
    const int np_base = blockIdx.x * NPB;
    {
        const int n0 = (np_base + tid) * 2;
        float f0a, f1a, f0b, f1b;
        mlp2(Y, n0,     sW1, sB1, sW2, sB2, sW3, sB3, f0a, f1a);
        mlp2(Y, n0 + 1, sW1, sB1, sW2, sB2, sW3, sB3, f0b, f1b);
        sF[tid] = make_float4(f0a, f1a, f0b, f1b);
    }

    __syncthreads();

    // ---- split-warp epilogue: warps 0-3 even si, warps 4-7 odd si.
    //      Each thread: 2 adjacent n-pairs = 32B contiguous -> 1KB per warp ----
    const int half = tid >> 7;            // 0: even si, 1: odd si
    const int gt   = tid & 127;           // index within half
    const float4 fA = sF[2 * gt + 0];     // f for n-pair 2*gt
    const float4 fB = sF[2 * gt + 1];     // f for n-pair 2*gt+1

    float4* op = reinterpret_cast<float4*>(out)
               + (size_t)(s_base + half) * NPAIRS + np_base + 2 * gt;
    #pragma unroll 8
    for (int si = half; si < SCHUNK; si += 2) {
        const float4 zz = sZ[si];          // conflict-free broadcast
        float4 v0, v1;
        v0.x = fmaf(fA.x, zz.x, fA.y * zz.z);
        v0.y = fmaf(fA.x, zz.y, fA.y * zz.w);
        v0.z = fmaf(fA.z, zz.x, fA.w * zz.z);
        v0.w = fmaf(fA.z, zz.y, fA.w * zz.w);
        v1.x = fmaf(fB.x, zz.x, fB.y * zz.z);
        v1.y = fmaf(fB.x, zz.y, fB.y * zz.w);
        v1.z = fmaf(fB.z, zz.x, fB.w * zz.z);
        v1.w = fmaf(fB.z, zz.y, fB.w * zz.w);
        __stcs(op,     v0);                // evict-first streaming stores
        __stcs(op + 1, v1);
        op += 2 * (size_t)NPAIRS;
    }
}

extern "C" void kernel_launch(void* const* d_in, const int* in_sizes, int n_in,
                              void* d_out, int out_size) {
    const float* eps   = (const float*)d_in[0];
    const float* mu    = (const float*)d_in[1];
    const float* sigma = (const float*)d_in[2];
    const float* x0    = (const float*)d_in[3];
    const float* ap    = (const float*)d_in[4];
    const float* bp    = (const float*)d_in[5];
    const float* Y     = (const float*)d_in[6];
    const float* W1    = (const float*)d_in[7];
    const float* b1    = (const float*)d_in[8];
    const float* W2    = (const float*)d_in[9];
    const float* b2    = (const float*)d_in[10];
    const float* W3    = (const float*)d_in[11];
    const float* b3    = (const float*)d_in[12];
    float* out = (float*)d_out;

    dim3 grid(NPAIRS / NPB, S_TOT / SCHUNK);   // (64, 16) = 1024 blocks
    encoder_fused_kernel<<<grid, TPB>>>(eps, mu, sigma, x0, ap, bp, Y,
                                        W1, b1, W2, b2, W3, b3, out);
}

// round 15
// speedup vs baseline: 1.8212x; 1.8212x over previous
#include <cuda_runtime.h>
#include <math.h>

#define S_TOT   2048
#define N_TOT   32768
#define NPAIRS  (N_TOT / 2)   // 16384 float4 columns
#define NFLOWS  30
#define SCHUNK  128           // s-samples handled per block
#define TPB     256           // one n-PAIR per thread -> 512 n per block

__device__ __forceinline__ float softplus_f(float x) {
    return (x > 0.0f) ? (x + log1pf(expf(-x))) : log1pf(expf(x));
}

// tiny 10->10->10->2 MLP with relu/relu/tanh, weights in smem
__device__ __forceinline__ void mlp2(const float* __restrict__ Y, int n,
                                     const float* sW1, const float* sB1,
                                     const float* sW2, const float* sB2,
                                     const float* sW3, const float* sB3,
                                     float& f0, float& f1) {
    float y[10];
    #pragma unroll
    for (int i = 0; i < 10; i++) y[i] = Y[n * 10 + i];
    float h1[10];
    #pragma unroll
    for (int j = 0; j < 10; j++) {
        float acc = sB1[j];
        #pragma unroll
        for (int i = 0; i < 10; i++) acc = fmaf(y[i], sW1[i * 10 + j], acc);
        h1[j] = fmaxf(acc, 0.0f);
    }
    float h2[10];
    #pragma unroll
    for (int j = 0; j < 10; j++) {
        float acc = sB2[j];
        #pragma unroll
        for (int i = 0; i < 10; i++) acc = fmaf(h1[i], sW2[i * 10 + j], acc);
        h2[j] = fmaxf(acc, 0.0f);
    }
    float a0 = sB3[0], a1 = sB3[1];
    #pragma unroll
    for (int j = 0; j < 10; j++) {
        a0 = fmaf(h2[j], sW3[j * 2 + 0], a0);
        a1 = fmaf(h2[j], sW3[j * 2 + 1], a1);
    }
    f0 = tanhf(a0);
    f1 = tanhf(a1);
}

__global__ __launch_bounds__(TPB)
void encoder_fused_kernel(
    const float* __restrict__ eps,      // [S,4]
    const float* __restrict__ mu,       // [4]
    const float* __restrict__ sigma,    // [4]
    const float* __restrict__ x0,       // [30,4]
    const float* __restrict__ ap,       // [30]
    const float* __restrict__ bp,       // [30]
    const float* __restrict__ Y,        // [N,10]
    const float* __restrict__ W1, const float* __restrict__ b1,
    const float* __restrict__ W2, const float* __restrict__ b2,
    const float* __restrict__ W3, const float* __restrict__ b3,
    float* __restrict__ out)            // [S,N,2]
{
    __shared__ float sW1[100], sW2[100], sW3[20];
    __shared__ float sB1[10], sB2[10], sB3[2];
    __shared__ float sx0[NFLOWS * 4];
    __shared__ float sAl[NFLOWS], sBe[NFLOWS];
    __shared__ float4 sZ[SCHUNK];

    const int tid = threadIdx.x;

    // ---- cooperative parameter staging ----
    if (tid < 100) { sW1[tid] = W1[tid]; sW2[tid] = W2[tid]; }
    if (tid < 20)  { sW3[tid] = W3[tid]; }
    if (tid < 10)  { sB1[tid] = b1[tid]; sB2[tid] = b2[tid]; }
    if (tid < 2)   { sB3[tid] = b3[tid]; }
    if (tid < NFLOWS * 4) { sx0[tid] = x0[tid]; }
    if (tid < NFLOWS) {
        float a = softplus_f(ap[tid]);
        sAl[tid] = a;
        sBe[tid] = -a + softplus_f(bp[tid]);
    }
    __syncthreads();

    // ---- radial flow for this block's s-chunk (threads 0..127) ----
    const int s_base = blockIdx.y * SCHUNK;
    if (tid < SCHUNK) {
        const int s = s_base + tid;
        const float4 e = reinterpret_cast<const float4*>(eps)[s];  // LDG.128
        float z0 = fmaf(tanhf(sigma[0]) + 1.0f, e.x, 3.0f * tanhf(mu[0]));
        float z1 = fmaf(tanhf(sigma[1]) + 1.0f, e.y, 3.0f * tanhf(mu[1]));
        float z2 = fmaf(tanhf(sigma[2]) + 1.0f, e.z, 3.0f * tanhf(mu[2]));
        float z3 = fmaf(tanhf(sigma[3]) + 1.0f, e.w, 3.0f * tanhf(mu[3]));
        #pragma unroll 1
        for (int k = 0; k < NFLOWS; k++) {
            const float a  = sAl[k];
            const float be = sBe[k];
            const float d0 = z0 - sx0[k * 4 + 0];
            const float d1 = z1 - sx0[k * 4 + 1];
            const float d2 = z2 - sx0[k * 4 + 2];
            const float d3 = z3 - sx0[k * 4 + 3];
            const float r  = sqrtf(fmaf(d0, d0, fmaf(d1, d1, fmaf(d2, d2, d3 * d3))));
            const float bh = __fdividef(be, a + r);   // fast rcp path
            z0 = fmaf(bh, d0, z0);
            z1 = fmaf(bh, d1, z1);
            z2 = fmaf(bh, d2, z2);
            z3 = fmaf(bh, d3, z3);
        }
        sZ[tid] = make_float4(z0, z1, z2, z3);
    }

    // ---- per-thread MLP for two adjacent n (overlaps flow warps' chain) ----
    const int np = blockIdx.x * TPB + tid;     // n-pair index
    const int n0 = np * 2;
    float f0a, f1a, f0b, f1b;
    mlp2(Y, n0,     sW1, sB1, sW2, sB2, sW3, sB3, f0a, f1a);
    mlp2(Y, n0 + 1, sW1, sB1, sW2, sB2, sW3, sB3, f0b, f1b);

    __syncthreads();

    // ---- store loop: 16B per thread per s -> lane-contiguous STG.128 ----
    float4* op = reinterpret_cast<float4*>(out) + (size_t)s_base * NPAIRS + np;
    #pragma unroll 16
    for (int si = 0; si < SCHUNK; si++) {
        const float4 zz = sZ[si];              // conflict-free broadcast
        float4 v;
        v.x = fmaf(f0a, zz.x, f1a * zz.z);
        v.y = fmaf(f0a, zz.y, f1a * zz.w);
        v.z = fmaf(f0b, zz.x, f1b * zz.z);
        v.w = fmaf(f0b, zz.y, f1b * zz.w);
        __stcs(op, v);                         // evict-first: output never re-read
        op += NPAIRS;
    }
}

extern "C" void kernel_launch(void* const* d_in, const int* in_sizes, int n_in,
                              void* d_out, int out_size) {
    const float* eps   = (const float*)d_in[0];
    const float* mu    = (const float*)d_in[1];
    const float* sigma = (const float*)d_in[2];
    const float* x0    = (const float*)d_in[3];
    const float* ap    = (const float*)d_in[4];
    const float* bp    = (const float*)d_in[5];
    const float* Y     = (const float*)d_in[6];
    const float* W1    = (const float*)d_in[7];
    const float* b1    = (const float*)d_in[8];
    const float* W2    = (const float*)d_in[9];
    const float* b2    = (const float*)d_in[10];
    const float* W3    = (const float*)d_in[11];
    const float* b3    = (const float*)d_in[12];
    float* out = (float*)d_out;

    dim3 grid(NPAIRS / TPB, S_TOT / SCHUNK);   // (64, 16) = 1024 blocks
    encoder_fused_kernel<<<grid, TPB>>>(eps, mu, sigma, x0, ap, bp, Y,
                                        W1, b1, W2, b2, W3, b3, out);
}